// round 2
// baseline (speedup 1.0000x reference)
#include <cuda_runtime.h>
#include <math.h>

#define NPTS 8192
#define BB   4
#define DD   128
#define KK   8
#define NB   (NPTS*BB)        // 32768
#define GST  132              // padded shared stride for GEMM tiles

// ---------------- scratch (device globals: allocation-free) ----------------
__device__ float g_qf[BB*NPTS*DD];   // [B,N,D]
__device__ float g_kf[BB*NPTS*DD];
__device__ float g_vf[BB*NPTS*DD];
__device__ float g_res[BB*NPTS*DD];
__device__ int   g_idx[BB*NPTS*KK];

// ---------------- f32x2 packed-FMA helpers (sm_100+) ----------------
__device__ __forceinline__ unsigned long long pack2(float lo, float hi) {
    unsigned long long r;
    asm("mov.b64 %0, {%1, %2};" : "=l"(r) : "f"(lo), "f"(hi));
    return r;
}
__device__ __forceinline__ unsigned long long fma2(unsigned long long a,
                                                   unsigned long long b,
                                                   unsigned long long c) {
    unsigned long long d;
    asm("fma.rn.f32x2 %0, %1, %2, %3;" : "=l"(d) : "l"(a), "l"(b), "l"(c));
    return d;
}
__device__ __forceinline__ void unpack2(unsigned long long p, float& lo, float& hi) {
    asm("mov.b64 {%0, %1}, %2;" : "=f"(lo), "=f"(hi) : "l"(p));
}

// ============================================================================
// GEMM: [32768,128] @ [128,128] (+bias, optional residual), f32x2 inner loop.
// mode 0/1/2: A=query [N,B,D] rows, out -> g_qf/g_kf/g_vf in [B,N,D]
// mode 3:     A=g_res permuted rows (b*N+n), out -> d_out [N,B,D] + residual
// ============================================================================
__global__ __launch_bounds__(256, 1) void gemm_k(
    const float* __restrict__ Aext, const float* __restrict__ W,
    const float* __restrict__ bias, const float* __restrict__ resid,
    float* __restrict__ outext, int mode)
{
    extern __shared__ float smbuf[];
    float* Ats = smbuf;               // [128][GST], transposed: Ats[j*GST+m]
    float* Ws  = smbuf + 128*GST;     // [128][GST]

    const float* A = (mode == 3) ? (const float*)g_res : Aext;
    float* outp = (mode == 0) ? (float*)g_qf :
                  (mode == 1) ? (float*)g_kf :
                  (mode == 2) ? (float*)g_vf : outext;

    const int tid = threadIdx.x;
    const int m0  = blockIdx.x * 128;

    #pragma unroll 8
    for (int i = tid; i < DD*DD; i += 256) {
        int j = i >> 7, d = i & 127;
        Ws[j*GST + d] = W[i];
    }
    #pragma unroll 8
    for (int i = tid; i < 128*DD; i += 256) {
        int m = i >> 7, j = i & 127;
        int gm = m0 + m;
        int arow = (mode == 3) ? ((gm & 3) * NPTS + (gm >> 2)) : gm;
        Ats[j*GST + m] = A[(size_t)arow*DD + j];
    }
    __syncthreads();

    const int tx = tid & 15, ty = tid >> 4;
    const int r0 = ty * 8, c0 = tx * 8;

    // acc2[rp][c]: row pair (2rp, 2rp+1) x col c, packed f32x2
    unsigned long long acc2[4][8];
    #pragma unroll
    for (int rp = 0; rp < 4; rp++)
        #pragma unroll
        for (int c = 0; c < 8; c++) acc2[rp][c] = 0ull;

    #pragma unroll 2
    for (int j = 0; j < 128; ++j) {
        // A row pairs: (r0,r0+1),(r0+2,r0+3),(r0+4,r0+5),(r0+6,r0+7)
        const ulonglong2 a01 = *(const ulonglong2*)(Ats + j*GST + r0);
        const ulonglong2 a45 = *(const ulonglong2*)(Ats + j*GST + r0 + 4);
        const float4 w0 = *(const float4*)(Ws + j*GST + c0);
        const float4 w1 = *(const float4*)(Ws + j*GST + c0 + 4);
        unsigned long long wd[8];
        wd[0]=pack2(w0.x,w0.x); wd[1]=pack2(w0.y,w0.y);
        wd[2]=pack2(w0.z,w0.z); wd[3]=pack2(w0.w,w0.w);
        wd[4]=pack2(w1.x,w1.x); wd[5]=pack2(w1.y,w1.y);
        wd[6]=pack2(w1.z,w1.z); wd[7]=pack2(w1.w,w1.w);
        unsigned long long av[4] = {a01.x, a01.y, a45.x, a45.y};
        #pragma unroll
        for (int rp = 0; rp < 4; rp++)
            #pragma unroll
            for (int c = 0; c < 8; c++)
                acc2[rp][c] = fma2(av[rp], wd[c], acc2[rp][c]);
    }

    float accf[8][8];
    #pragma unroll
    for (int rp = 0; rp < 4; rp++)
        #pragma unroll
        for (int c = 0; c < 8; c++)
            unpack2(acc2[rp][c], accf[2*rp][c], accf[2*rp+1][c]);

    float bv[8];
    #pragma unroll
    for (int c = 0; c < 8; c++) bv[c] = bias[c0 + c];

    #pragma unroll
    for (int r = 0; r < 8; r++) {
        int gm = m0 + r0 + r;
        float* orow;
        const float* rrow = 0;
        if (mode < 3) {
            orow = outp + (size_t)((gm & 3) * NPTS + (gm >> 2)) * DD;
        } else {
            orow = outp + (size_t)gm * DD;
            rrow = resid + (size_t)gm * DD;
        }
        #pragma unroll
        for (int c = 0; c < 8; c++) {
            float v = accf[r][c] + bv[c];
            if (mode == 3) v += rrow[c0 + c];
            orow[c0 + c] = v;
        }
    }
}

// ============================================================================
// Brute-force KNN, 4-way candidate split per query.
// Block: 256 threads = 64 queries x 4 splits. Each split scans NPTS/4
// candidates keeping a sorted top-8; partials merged in shared memory.
// ============================================================================
__global__ __launch_bounds__(256, 1) void knn_k(const float* __restrict__ pos)
{
    __shared__ float4 cand[1024];
    __shared__ float  sd[256*8];
    __shared__ int    si[256*8];

    const int b = blockIdx.y;
    const int t = threadIdx.x;
    const int q = blockIdx.x * 64 + (t >> 2);
    const int s = t & 3;
    const float* pb = pos + (size_t)b * NPTS * 3;

    const float qx = pb[q*3], qy = pb[q*3+1], qz = pb[q*3+2];
    const float qsq = fmaf(qz, qz, fmaf(qy, qy, qx*qx));

    float bd[8]; int bi[8];
    #pragma unroll
    for (int k = 0; k < 8; k++) { bd[k] = 1e30f; bi[k] = 0x7fffffff; }

    const int base = s * 256;
    for (int t0 = 0; t0 < NPTS; t0 += 1024) {
        __syncthreads();
        #pragma unroll
        for (int i = t; i < 1024; i += 256) {
            float x = pb[(t0+i)*3], y = pb[(t0+i)*3+1], z = pb[(t0+i)*3+2];
            cand[i] = make_float4(x, y, z, fmaf(z, z, fmaf(y, y, x*x)));
        }
        __syncthreads();
        #pragma unroll 4
        for (int m = 0; m < 256; ++m) {
            float4 c = cand[base + m];
            float dot = fmaf(qz, c.z, fmaf(qy, c.y, qx * c.x));
            float d2  = fmaf(-2.f, dot, qsq + c.w);
            if (d2 < bd[7]) {
                bd[7] = d2; bi[7] = t0 + base + m;
                #pragma unroll
                for (int r = 7; r > 0; --r) {
                    if (bd[r] < bd[r-1]) {
                        float td = bd[r]; bd[r] = bd[r-1]; bd[r-1] = td;
                        int   ti = bi[r]; bi[r] = bi[r-1]; bi[r-1] = ti;
                    }
                }
            }
        }
    }

    #pragma unroll
    for (int k = 0; k < 8; k++) { sd[t*8+k] = bd[k]; si[t*8+k] = bi[k]; }
    __syncthreads();

    if (s == 0) {
        // 4-way merge of sorted lists at threads t..t+3
        int p0 = 0, p1 = 0, p2 = 0, p3 = 0;
        int* op = g_idx + ((size_t)b * NPTS + q) * KK;
        #pragma unroll
        for (int o = 0; o < 8; ++o) {
            float d0 = sd[(t+0)*8+p0], d1 = sd[(t+1)*8+p1];
            float d2 = sd[(t+2)*8+p2], d3 = sd[(t+3)*8+p3];
            int   i0 = si[(t+0)*8+p0], i1 = si[(t+1)*8+p1];
            int   i2 = si[(t+2)*8+p2], i3 = si[(t+3)*8+p3];
            // lexicographic min over (d, idx)
            int sa = (d1 < d0 || (d1 == d0 && i1 < i0)) ? 1 : 0;
            float da = sa ? d1 : d0; int ia = sa ? i1 : i0;
            int sb = (d3 < d2 || (d3 == d2 && i3 < i2)) ? 3 : 2;
            float db = sb ? 0 : 0; db = (sb == 3) ? d3 : d2; int ib = (sb == 3) ? i3 : i2;
            int pick = (db < da || (db == da && ib < ia)) ? sb : sa;
            op[o] = (pick == 0) ? i0 : (pick == 1) ? i1 : (pick == 2) ? i2 : i3;
            if      (pick == 0) p0++;
            else if (pick == 1) p1++;
            else if (pick == 2) p2++;
            else                p3++;
        }
    }
}

// ============================================================================
// Fused per-point kernel with f32x2 packed FMA in the two 128-dot phases.
// 512 threads = 4 sub-blocks of 128; each sub-block owns one point.
// ============================================================================
#define FSM_WP2 0
#define FSM_WG  16384
#define FSM_WP1 32768
#define FSM_BP1 33152
#define FSM_BP2 33280
#define FSM_BG  33408
#define FSM_H   33536
#define FSM_U   37632
#define FSM_REL 41728
#define FSM_RA  41856
#define FSM_RB  41984
#define FSM_IDX 42112
#define FUSED_SMEM_FLOATS 42144
#define FUSED_SMEM_BYTES  (FUSED_SMEM_FLOATS*4)

__global__ __launch_bounds__(512, 1) void fused_k(
    const float* __restrict__ pos,
    const float* __restrict__ Wp1, const float* __restrict__ bp1,
    const float* __restrict__ Wp2, const float* __restrict__ bp2,
    const float* __restrict__ Wg,  const float* __restrict__ bg,
    int nTasks)
{
    extern __shared__ float sm[];
    float* Wp2s = sm + FSM_WP2;
    float* Wgs  = sm + FSM_WG;
    float* Wp1s = sm + FSM_WP1;
    float* bp1s = sm + FSM_BP1;
    float* bp2s = sm + FSM_BP2;
    float* bgs  = sm + FSM_BG;

    const int tid  = threadIdx.x;
    const int sub  = tid >> 7;
    const int d    = tid & 127;
    const int lane = tid & 31;
    const int wsub = (tid >> 5) & 3;

    for (int i = tid; i < DD*DD; i += 512) { Wp2s[i] = Wp2[i]; Wgs[i] = Wg[i]; }
    for (int i = tid; i < 3*DD; i += 512) Wp1s[i] = Wp1[i];
    if (tid < DD) { bp1s[tid] = bp1[tid]; bp2s[tid] = bp2[tid]; bgs[tid] = bg[tid]; }
    __syncthreads();

    float* my_h   = sm + FSM_H   + sub * 1024;   // [j][k], stride 8
    float* my_u   = sm + FSM_U   + sub * 1024;
    float* my_rel = sm + FSM_REL + sub * 32;
    float* my_rA  = sm + FSM_RA  + sub * 32;
    float* my_rB  = sm + FSM_RB  + sub * 32;
    int*   my_idx = (int*)(sm + FSM_IDX) + sub * 8;

    const float w0 = Wp1s[d], w1 = Wp1s[128 + d], w2 = Wp1s[256 + d];
    const float bb1 = bp1s[d], bb2 = bp2s[d], bbg = bgs[d];
    const float scale = 0.08838834764831845f;    // 1/sqrt(128)

    for (int task = blockIdx.x; task < nTasks; task += gridDim.x) {
        const int g = task * 4 + sub;
        const int b = g >> 13;
        const int n = g & (NPTS - 1);
        const float* kbase = g_kf + (size_t)b * NPTS * DD;
        const float* vbase = g_vf + (size_t)b * NPTS * DD;

        if (d < 8) {
            int id = g_idx[(size_t)g * KK + d];
            my_idx[d] = id;
            const float* pb = pos + (size_t)b * NPTS * 3;
            my_rel[d*4+0] = pb[n*3+0] - pb[id*3+0];
            my_rel[d*4+1] = pb[n*3+1] - pb[id*3+1];
            my_rel[d*4+2] = pb[n*3+2] - pb[id*3+2];
        }
        __syncthreads();

        // phase 1: h[j=d][k] = gelu(rel[k] . Wp1[:,d] + bp1[d])
        #pragma unroll
        for (int k = 0; k < 8; ++k) {
            float z = fmaf(my_rel[k*4+2], w2,
                      fmaf(my_rel[k*4+1], w1,
                      fmaf(my_rel[k*4+0], w0, bb1)));
            my_h[d*8 + k] = 0.5f * z * (1.f + erff(z * 0.70710678118654752f));
        }
        __syncthreads();

        // phase 2: pe[k] (feature d) = h[k] . Wp2[:,d] + bp2[d]  (f32x2)
        unsigned long long pe01, pe23, pe45, pe67;
        pe01 = pe23 = pe45 = pe67 = pack2(bb2, bb2);
        {
            const float* wp = Wp2s + d;
            const ulonglong2* hp = (const ulonglong2*)my_h;
            #pragma unroll 4
            for (int j = 0; j < 128; ++j) {
                float w = wp[j * 128];
                unsigned long long wd = pack2(w, w);
                ulonglong2 h0 = hp[2*j];
                ulonglong2 h1 = hp[2*j + 1];
                pe01 = fma2(h0.x, wd, pe01);
                pe23 = fma2(h0.y, wd, pe23);
                pe45 = fma2(h1.x, wd, pe45);
                pe67 = fma2(h1.y, wd, pe67);
            }
        }
        float pe[8];
        unpack2(pe01, pe[0], pe[1]); unpack2(pe23, pe[2], pe[3]);
        unpack2(pe45, pe[4], pe[5]); unpack2(pe67, pe[6], pe[7]);

        // build u[j=d][k] = q[d] - k_knn[k][d] + pe[k]
        {
            float qv = g_qf[((size_t)b * NPTS + n) * DD + d];
            #pragma unroll
            for (int k = 0; k < 8; ++k) {
                float kv = kbase[(size_t)my_idx[k] * DD + d];
                my_u[d*8 + k] = qv - kv + pe[k];
            }
        }
        __syncthreads();

        // phase 3: a[k] (feature d) = u[k] . Wg[:,d] + bg[d]  (f32x2)
        unsigned long long a01, a23, a45, a67;
        a01 = a23 = a45 = a67 = pack2(bbg, bbg);
        {
            const float* wp = Wgs + d;
            const ulonglong2* up = (const ulonglong2*)my_u;
            #pragma unroll 4
            for (int j = 0; j < 128; ++j) {
                float w = wp[j * 128];
                unsigned long long wd = pack2(w, w);
                ulonglong2 u0 = up[2*j];
                ulonglong2 u1 = up[2*j + 1];
                a01 = fma2(u0.x, wd, a01);
                a23 = fma2(u0.y, wd, a23);
                a45 = fma2(u1.x, wd, a45);
                a67 = fma2(u1.y, wd, a67);
            }
        }
        float a[8];
        unpack2(a01, a[0], a[1]); unpack2(a23, a[2], a[3]);
        unpack2(a45, a[4], a[5]); unpack2(a67, a[6], a[7]);

        #pragma unroll
        for (int k = 0; k < 8; ++k) a[k] *= scale;

        // softmax over feature dim (128 threads) for each k
        float red[8];
        #pragma unroll
        for (int k = 0; k < 8; ++k) red[k] = a[k];
        #pragma unroll
        for (int off = 16; off > 0; off >>= 1)
            #pragma unroll
            for (int k = 0; k < 8; ++k)
                red[k] = fmaxf(red[k], __shfl_xor_sync(0xffffffffu, red[k], off));
        if (lane == 0) {
            #pragma unroll
            for (int k = 0; k < 8; ++k) my_rA[wsub*8 + k] = red[k];
        }
        __syncthreads();

        float e[8];
        #pragma unroll
        for (int k = 0; k < 8; ++k) {
            float bm = fmaxf(fmaxf(my_rA[k], my_rA[8+k]), fmaxf(my_rA[16+k], my_rA[24+k]));
            e[k] = __expf(a[k] - bm);
            red[k] = e[k];
        }
        #pragma unroll
        for (int off = 16; off > 0; off >>= 1)
            #pragma unroll
            for (int k = 0; k < 8; ++k)
                red[k] += __shfl_xor_sync(0xffffffffu, red[k], off);
        if (lane == 0) {
            #pragma unroll
            for (int k = 0; k < 8; ++k) my_rB[wsub*8 + k] = red[k];
        }
        __syncthreads();

        float rsum = 0.f;
        #pragma unroll
        for (int k = 0; k < 8; ++k) {
            float tot = (my_rB[k] + my_rB[8+k]) + (my_rB[16+k] + my_rB[24+k]);
            float smx = e[k] / tot;
            float v = vbase[(size_t)my_idx[k] * DD + d];
            rsum = fmaf(smx, v + pe[k], rsum);
        }
        g_res[((size_t)b * NPTS + n) * DD + d] = rsum;
        __syncthreads();
    }
}

// ============================================================================
// host launch
// ============================================================================
#define GEMM_SMEM (2*128*GST*4)

extern "C" void kernel_launch(void* const* d_in, const int* in_sizes, int n_in,
                              void* d_out, int out_size)
{
    const float* query = (const float*)d_in[0];
    const float* pos   = (const float*)d_in[1];
    const float* Wq  = (const float*)d_in[2];  const float* bq  = (const float*)d_in[3];
    const float* Wk  = (const float*)d_in[4];  const float* bk  = (const float*)d_in[5];
    const float* Wv  = (const float*)d_in[6];  const float* bv  = (const float*)d_in[7];
    const float* Wp1 = (const float*)d_in[8];  const float* bp1 = (const float*)d_in[9];
    const float* Wp2 = (const float*)d_in[10]; const float* bp2 = (const float*)d_in[11];
    const float* Wg  = (const float*)d_in[12]; const float* bg  = (const float*)d_in[13];
    const float* Wo  = (const float*)d_in[14]; const float* bo  = (const float*)d_in[15];
    float* out = (float*)d_out;

    cudaFuncSetAttribute(gemm_k,  cudaFuncAttributeMaxDynamicSharedMemorySize, GEMM_SMEM);
    cudaFuncSetAttribute(fused_k, cudaFuncAttributeMaxDynamicSharedMemorySize, FUSED_SMEM_BYTES);

    int dev = 0, sms = 148;
    cudaGetDevice(&dev);
    cudaDeviceGetAttribute(&sms, cudaDevAttrMultiProcessorCount, dev);

    // QKV projections -> g_qf/g_kf/g_vf in [B,N,D]
    gemm_k<<<NB/128, 256, GEMM_SMEM>>>(query, Wq, bq, (const float*)0, (float*)0, 0);
    gemm_k<<<NB/128, 256, GEMM_SMEM>>>(query, Wk, bk, (const float*)0, (float*)0, 1);
    gemm_k<<<NB/128, 256, GEMM_SMEM>>>(query, Wv, bv, (const float*)0, (float*)0, 2);

    // KNN indices (4-way split per query)
    knn_k<<<dim3(NPTS/64, BB), 256>>>(pos);

    // fused per-point attention
    fused_k<<<sms, 512, FUSED_SMEM_BYTES>>>(pos, Wp1, bp1, Wp2, bp2, Wg, bg, NB/4);

    // output projection + residual -> [N,B,D]
    gemm_k<<<NB/128, 256, GEMM_SMEM>>>(query, Wo, bo, query, out, 3);
}